// round 1
// baseline (speedup 1.0000x reference)
#include <cuda_runtime.h>
#include <cuda_bf16.h>
#include <cstdint>

#define NN   100000
#define EE   1600000
#define FIN  256
#define HID  128
#define NC   16
#define ETOT (EE + NN)   // edges + self loops

// ---------------- scratch (device globals: no allocations allowed) ----------
static __device__ float g_h[(size_t)NN * HID];     // x @ W1
static __device__ float g_agg1[(size_t)NN * HID];  // aggregated layer-1
static __device__ float g_z[(size_t)NN * NC];      // relu(h1) @ W2
static __device__ float g_norm[ETOT];              // dinv[src]*dinv[dst]
static __device__ float g_dinv[NN];
static __device__ int   g_deg[NN];

// ---------------- degree / normalization ------------------------------------
__global__ void k_deg_init() {
    int i = blockIdx.x * blockDim.x + threadIdx.x;
    if (i < NN) g_deg[i] = 1;   // self loop
}

__global__ void k_deg_count(const int* __restrict__ dst) {
    int e = blockIdx.x * blockDim.x + threadIdx.x;
    if (e < EE) atomicAdd(&g_deg[dst[e]], 1);
}

__global__ void k_dinv() {
    int i = blockIdx.x * blockDim.x + threadIdx.x;
    if (i < NN) g_dinv[i] = rsqrtf((float)g_deg[i]);
}

__global__ void k_norm(const int* __restrict__ src, const int* __restrict__ dst) {
    int e = blockIdx.x * blockDim.x + threadIdx.x;
    if (e < EE) {
        g_norm[e] = g_dinv[src[e]] * g_dinv[dst[e]];
    } else if (e < ETOT) {
        float v = g_dinv[e - EE];
        g_norm[e] = v * v;
    }
}

// ---------------- zero / init kernels ---------------------------------------
__global__ void k_zero_agg1() {
    size_t i = (size_t)(blockIdx.x * blockDim.x + threadIdx.x) * 4;
    if (i < (size_t)NN * HID)
        *(float4*)&g_agg1[i] = make_float4(0.f, 0.f, 0.f, 0.f);
}

__global__ void k_init_out(const float* __restrict__ b2, float* __restrict__ out) {
    int i = blockIdx.x * blockDim.x + threadIdx.x;
    if (i < NN * NC) out[i] = b2[i & (NC - 1)];
}

// ---------------- GEMM1: g_h = x[N,256] @ W1[256,128] -----------------------
// 128x128 block tile, BK=8, 256 threads, 8x8 register microtile.
__global__ __launch_bounds__(256) void k_gemm1(const float* __restrict__ A,
                                               const float* __restrict__ B) {
    __shared__ float As[8][128];
    __shared__ float Bs[8][128];
    const int tid = threadIdx.x;
    const int blockM = blockIdx.x * 128;

    const int tm = (tid >> 4) * 8;   // 0..120
    const int tn = (tid & 15) * 8;   // 0..120

    const int aRow = tid >> 1;          // 0..127
    const int aK   = (tid & 1) * 4;     // 0 or 4
    const int bK   = tid >> 5;          // 0..7
    const int bN   = (tid & 31) * 4;    // 0..124
    const int gRow = blockM + aRow;

    float acc[8][8];
    #pragma unroll
    for (int i = 0; i < 8; i++)
        #pragma unroll
        for (int j = 0; j < 8; j++) acc[i][j] = 0.f;

    for (int k0 = 0; k0 < FIN; k0 += 8) {
        float4 av = make_float4(0.f, 0.f, 0.f, 0.f);
        if (gRow < NN) av = *(const float4*)&A[(size_t)gRow * FIN + k0 + aK];
        As[aK + 0][aRow] = av.x;
        As[aK + 1][aRow] = av.y;
        As[aK + 2][aRow] = av.z;
        As[aK + 3][aRow] = av.w;

        float4 bv = *(const float4*)&B[(size_t)(k0 + bK) * HID + bN];
        *(float4*)&Bs[bK][bN] = bv;
        __syncthreads();

        #pragma unroll
        for (int k = 0; k < 8; k++) {
            float ra[8], rb[8];
            #pragma unroll
            for (int i = 0; i < 8; i++) ra[i] = As[k][tm + i];
            #pragma unroll
            for (int j = 0; j < 8; j++) rb[j] = Bs[k][tn + j];
            #pragma unroll
            for (int i = 0; i < 8; i++)
                #pragma unroll
                for (int j = 0; j < 8; j++) acc[i][j] += ra[i] * rb[j];
        }
        __syncthreads();
    }

    #pragma unroll
    for (int i = 0; i < 8; i++) {
        int r = blockM + tm + i;
        if (r < NN) {
            #pragma unroll
            for (int j = 0; j < 8; j += 4) {
                float4 v = make_float4(acc[i][j], acc[i][j+1], acc[i][j+2], acc[i][j+3]);
                *(float4*)&g_h[(size_t)r * HID + tn + j] = v;
            }
        }
    }
}

// ---------------- aggregate layer 1: warp per edge, red.v4 ------------------
__global__ __launch_bounds__(256) void k_agg1(const int* __restrict__ src,
                                              const int* __restrict__ dst) {
    int w = (blockIdx.x * blockDim.x + threadIdx.x) >> 5;
    int lane = threadIdx.x & 31;
    if (w >= ETOT) return;
    int s, d;
    if (w < EE) { s = src[w]; d = dst[w]; }
    else        { s = d = w - EE; }
    float nrm = g_norm[w];

    float4 v = *(const float4*)&g_h[(size_t)s * HID + lane * 4];
    v.x *= nrm; v.y *= nrm; v.z *= nrm; v.w *= nrm;

    float* p = &g_agg1[(size_t)d * HID + lane * 4];
    asm volatile("red.global.add.v4.f32 [%0], {%1,%2,%3,%4};"
                 :: "l"(p), "f"(v.x), "f"(v.y), "f"(v.z), "f"(v.w)
                 : "memory");
}

// ---------------- GEMM2 (fused bias + relu): g_z = relu(agg1+b1) @ W2 -------
__global__ __launch_bounds__(256) void k_gemm2(const float* __restrict__ b1,
                                               const float* __restrict__ W2) {
    __shared__ float sW[HID * NC];
    __shared__ float sb[HID];
    int tid = threadIdx.x;
    #pragma unroll
    for (int i = tid; i < HID * NC; i += 256) sW[i] = W2[i];
    if (tid < HID) sb[tid] = b1[tid];
    __syncthreads();

    int node = blockIdx.x * 16 + (tid >> 4);
    int c = tid & 15;
    if (node >= NN) return;

    const float* row = &g_agg1[(size_t)node * HID];
    float acc = 0.f;
    #pragma unroll 8
    for (int k = 0; k < HID; k++) {
        float a = row[k] + sb[k];
        a = a > 0.f ? a : 0.f;
        acc += a * sW[k * NC + c];
    }
    g_z[(size_t)node * NC + c] = acc;
}

// ---------------- aggregate layer 2: 4 threads per edge, red.v4 -------------
__global__ __launch_bounds__(256) void k_agg2(const int* __restrict__ src,
                                              const int* __restrict__ dst,
                                              float* __restrict__ out) {
    int gid = blockIdx.x * blockDim.x + threadIdx.x;
    int e = gid >> 2;
    int ch = gid & 3;
    if (e >= ETOT) return;
    int s, d;
    if (e < EE) { s = src[e]; d = dst[e]; }
    else        { s = d = e - EE; }
    float nrm = g_norm[e];

    float4 v = *(const float4*)&g_z[(size_t)s * NC + ch * 4];
    v.x *= nrm; v.y *= nrm; v.z *= nrm; v.w *= nrm;

    float* p = &out[(size_t)d * NC + ch * 4];
    asm volatile("red.global.add.v4.f32 [%0], {%1,%2,%3,%4};"
                 :: "l"(p), "f"(v.x), "f"(v.y), "f"(v.z), "f"(v.w)
                 : "memory");
}

// ---------------- launch -----------------------------------------------------
extern "C" void kernel_launch(void* const* d_in, const int* in_sizes, int n_in,
                              void* d_out, int out_size) {
    const float* x  = (const float*)d_in[0];
    const int*   ei = (const int*)d_in[1];
    const float* W1 = (const float*)d_in[2];
    const float* b1 = (const float*)d_in[3];
    const float* W2 = (const float*)d_in[4];
    const float* b2 = (const float*)d_in[5];
    float* out = (float*)d_out;

    const int* src = ei;        // edge_index[0]
    const int* dst = ei + EE;   // edge_index[1]

    k_deg_init<<<(NN + 255) / 256, 256>>>();
    k_deg_count<<<(EE + 255) / 256, 256>>>(dst);
    k_dinv<<<(NN + 255) / 256, 256>>>();
    k_norm<<<(ETOT + 255) / 256, 256>>>(src, dst);

    k_zero_agg1<<<((NN * HID / 4) + 255) / 256, 256>>>();

    k_gemm1<<<(NN + 127) / 128, 256>>>(x, W1);

    // one warp per edge: ETOT warps, 8 warps per block
    k_agg1<<<ETOT / 8, 256>>>(src, dst);

    k_gemm2<<<NN / 16, 256>>>(b1, W2);

    k_init_out<<<(NN * NC + 255) / 256, 256>>>(b2, out);

    // 4 threads per edge
    k_agg2<<<(ETOT * 4 + 255) / 256, 256>>>(src, dst, out);
}

// round 2
// speedup vs baseline: 1.1855x; 1.1855x over previous
#include <cuda_runtime.h>
#include <cuda_bf16.h>
#include <cstdint>

#define NN   100000
#define EE   1600000
#define FIN  256
#define HID  128
#define NC   16

// ---------------- scratch ----------------------------------------------------
static __device__ float g_h[(size_t)NN * HID];     // h' = (x@W1) * dinv[row]
static __device__ float g_agg1[(size_t)NN * HID];  // init h'[i], += h'[src]
static __device__ float g_z[(size_t)NN * NC];      // z' = (relu(...)@W2)*dinv
static __device__ float g_dinv[NN];
static __device__ int   g_deg[NN];

// ---------------- degree / normalization ------------------------------------
__global__ void k_deg_init() {
    int i = blockIdx.x * blockDim.x + threadIdx.x;
    if (i < NN) g_deg[i] = 1;   // self loop
}
__global__ void k_deg_count(const int* __restrict__ dst) {
    int e = blockIdx.x * blockDim.x + threadIdx.x;
    if (e < EE) atomicAdd(&g_deg[dst[e]], 1);
}
__global__ void k_dinv() {
    int i = blockIdx.x * blockDim.x + threadIdx.x;
    if (i < NN) g_dinv[i] = rsqrtf((float)g_deg[i]);
}

// ---------------- tf32 helpers -----------------------------------------------
__device__ __forceinline__ float tf32_rna(float v) {
    uint32_t u;
    asm("cvt.rna.tf32.f32 %0, %1;" : "=r"(u) : "f"(v));
    return __uint_as_float(u);
}
__device__ __forceinline__ void mma_tf32(float* d, const uint32_t* a, const uint32_t* b) {
    asm volatile(
        "mma.sync.aligned.m16n8k8.row.col.f32.tf32.tf32.f32 "
        "{%0,%1,%2,%3}, {%4,%5,%6,%7}, {%8,%9}, {%0,%1,%2,%3};"
        : "+f"(d[0]), "+f"(d[1]), "+f"(d[2]), "+f"(d[3])
        : "r"(a[0]), "r"(a[1]), "r"(a[2]), "r"(a[3]), "r"(b[0]), "r"(b[1]));
}

// ---------------- GEMM1: g_h = (x[N,256] @ W1[256,128]) * dinv ---------------
// 128x128 block tile, BK=16, 256 threads (8 warps: 2Mx4N, warp tile 64x32).
// 3xTF32 split: hi*hi + lo*hi + hi*lo  (~fp32 accuracy).
__global__ __launch_bounds__(256) void k_gemm1(const float* __restrict__ A,
                                               const float* __restrict__ B) {
    __shared__ float As[2][128][20];   // [buf][row][k] pad->conflict-free frags
    __shared__ float Bs[2][16][132];   // [buf][k][n]

    const int tid  = threadIdx.x;
    const int warp = tid >> 5, lane = tid & 31;
    const int blockM = blockIdx.x * 128;
    const int wm = (warp >> 2) * 64;   // 0 / 64
    const int wn = (warp & 3) * 32;    // 0..96

    float acc[4][4][4];
    #pragma unroll
    for (int i = 0; i < 4; i++)
        #pragma unroll
        for (int j = 0; j < 4; j++)
            #pragma unroll
            for (int q = 0; q < 4; q++) acc[i][j][q] = 0.f;

    float4 aReg[2], bReg[2];

    auto loadChunk = [&](int k0) {
        #pragma unroll
        for (int i = 0; i < 2; i++) {
            int idx = tid + 256 * i;
            int r = idx >> 2, c = (idx & 3) * 4;
            int gr = blockM + r;
            aReg[i] = (gr < NN) ? *(const float4*)&A[(size_t)gr * FIN + k0 + c]
                                : make_float4(0.f, 0.f, 0.f, 0.f);
            int bk = idx >> 5, bc = (idx & 31) * 4;
            bReg[i] = *(const float4*)&B[(size_t)(k0 + bk) * HID + bc];
        }
    };
    auto storeChunk = [&](int buf) {
        #pragma unroll
        for (int i = 0; i < 2; i++) {
            int idx = tid + 256 * i;
            int r = idx >> 2, c = (idx & 3) * 4;
            *(float4*)&As[buf][r][c] = aReg[i];
            int bk = idx >> 5, bc = (idx & 31) * 4;
            *(float4*)&Bs[buf][bk][bc] = bReg[i];
        }
    };

    loadChunk(0);
    storeChunk(0);
    __syncthreads();

    for (int ch = 0; ch < 16; ch++) {
        const int buf = ch & 1;
        if (ch < 15) loadChunk((ch + 1) * 16);

        #pragma unroll
        for (int ks = 0; ks < 2; ks++) {
            const int kk = ks * 8;
            uint32_t ah[4][4], al[4][4];
            #pragma unroll
            for (int mt = 0; mt < 4; mt++) {
                int r = wm + mt * 16 + (lane >> 2);
                int c = kk + (lane & 3);
                float v0 = As[buf][r][c];
                float v1 = As[buf][r + 8][c];
                float v2 = As[buf][r][c + 4];
                float v3 = As[buf][r + 8][c + 4];
                float h0 = tf32_rna(v0), h1 = tf32_rna(v1),
                      h2 = tf32_rna(v2), h3 = tf32_rna(v3);
                ah[mt][0] = __float_as_uint(h0); al[mt][0] = __float_as_uint(tf32_rna(v0 - h0));
                ah[mt][1] = __float_as_uint(h1); al[mt][1] = __float_as_uint(tf32_rna(v1 - h1));
                ah[mt][2] = __float_as_uint(h2); al[mt][2] = __float_as_uint(tf32_rna(v2 - h2));
                ah[mt][3] = __float_as_uint(h3); al[mt][3] = __float_as_uint(tf32_rna(v3 - h3));
            }
            uint32_t bh[4][2], bl[4][2];
            #pragma unroll
            for (int nt = 0; nt < 4; nt++) {
                int n = wn + nt * 8 + (lane >> 2);
                int k = kk + (lane & 3);
                float v0 = Bs[buf][k][n];
                float v1 = Bs[buf][k + 4][n];
                float h0 = tf32_rna(v0), h1 = tf32_rna(v1);
                bh[nt][0] = __float_as_uint(h0); bl[nt][0] = __float_as_uint(tf32_rna(v0 - h0));
                bh[nt][1] = __float_as_uint(h1); bl[nt][1] = __float_as_uint(tf32_rna(v1 - h1));
            }
            #pragma unroll
            for (int mt = 0; mt < 4; mt++)
                #pragma unroll
                for (int nt = 0; nt < 4; nt++) {
                    mma_tf32(acc[mt][nt], ah[mt], bh[nt]);
                    mma_tf32(acc[mt][nt], al[mt], bh[nt]);
                    mma_tf32(acc[mt][nt], ah[mt], bl[nt]);
                }
        }

        if (ch < 15) storeChunk(buf ^ 1);
        __syncthreads();
    }

    // epilogue: scale by dinv[row], write to g_h AND g_agg1 (self-loop init)
    #pragma unroll
    for (int mt = 0; mt < 4; mt++) {
        #pragma unroll
        for (int half = 0; half < 2; half++) {
            int r = blockM + wm + mt * 16 + (lane >> 2) + half * 8;
            if (r < NN) {
                float di = g_dinv[r];
                #pragma unroll
                for (int nt = 0; nt < 4; nt++) {
                    int c = wn + nt * 8 + 2 * (lane & 3);
                    float2 v = make_float2(acc[mt][nt][half * 2 + 0] * di,
                                           acc[mt][nt][half * 2 + 1] * di);
                    *(float2*)&g_h[(size_t)r * HID + c]    = v;
                    *(float2*)&g_agg1[(size_t)r * HID + c] = v;
                }
            }
        }
    }
}

// ---------------- aggregate layer 1: warp per edge, red.v4 ------------------
__global__ __launch_bounds__(256) void k_agg1(const int* __restrict__ src,
                                              const int* __restrict__ dst) {
    int w = (blockIdx.x * blockDim.x + threadIdx.x) >> 5;
    int lane = threadIdx.x & 31;
    if (w >= EE) return;
    int s = __ldg(&src[w]);
    int d = __ldg(&dst[w]);
    float4 v = *(const float4*)&g_h[(size_t)s * HID + lane * 4];
    float* p = &g_agg1[(size_t)d * HID + lane * 4];
    asm volatile("red.global.add.v4.f32 [%0], {%1,%2,%3,%4};"
                 :: "l"(p), "f"(v.x), "f"(v.y), "f"(v.z), "f"(v.w)
                 : "memory");
}

// ---------------- GEMM2: z' = (relu(dinv*agg1 + b1) @ W2) * dinv ------------
// 16 nodes per 256-thread block; rows staged in shared (read once).
__global__ __launch_bounds__(256) void k_gemm2(const float* __restrict__ b1,
                                               const float* __restrict__ W2,
                                               float* __restrict__ out) {
    __shared__ float sRow[16][132];
    __shared__ float sW[HID * NC];
    __shared__ float sB1[HID];
    __shared__ float sDi[16];
    const int tid = threadIdx.x;
    const int nb = blockIdx.x * 16;

    #pragma unroll
    for (int i = 0; i < 2; i++) {
        int idx = tid + 256 * i;
        int r = idx >> 5, c = (idx & 31) * 4;
        int node = nb + r;
        float4 v = (node < NN) ? *(const float4*)&g_agg1[(size_t)node * HID + c]
                               : make_float4(0.f, 0.f, 0.f, 0.f);
        *(float4*)&sRow[r][c] = v;
    }
    for (int i = tid; i < HID * NC; i += 256) sW[i] = W2[i];
    if (tid < HID) sB1[tid] = b1[tid];
    if (tid < 16) { int node = nb + tid; sDi[tid] = (node < NN) ? g_dinv[node] : 0.f; }
    __syncthreads();

    int ln = tid >> 4, c = tid & 15;
    int node = nb + ln;
    if (node >= NN) return;
    float di = sDi[ln];
    float acc = 0.f;
    #pragma unroll
    for (int k = 0; k < HID; k++) {
        float a = fmaf(sRow[ln][k], di, sB1[k]);
        a = fmaxf(a, 0.f);
        acc = fmaf(a, sW[k * NC + c], acc);
    }
    float zp = acc * di;
    g_z[(size_t)node * NC + c] = zp;   // gather source
    out[(size_t)node * NC + c] = zp;   // self-loop init of accumulator
}

// ---------------- aggregate layer 2: 4 threads per edge, red.v4 -------------
__global__ __launch_bounds__(256) void k_agg2(const int* __restrict__ src,
                                              const int* __restrict__ dst,
                                              float* __restrict__ out) {
    int gid = blockIdx.x * blockDim.x + threadIdx.x;
    int e = gid >> 2;
    if (e >= EE) return;
    int q = gid & 3;
    int s = __ldg(&src[e]);
    int d = __ldg(&dst[e]);
    float4 v = *(const float4*)&g_z[(size_t)s * NC + q * 4];
    float* p = &out[(size_t)d * NC + q * 4];
    asm volatile("red.global.add.v4.f32 [%0], {%1,%2,%3,%4};"
                 :: "l"(p), "f"(v.x), "f"(v.y), "f"(v.z), "f"(v.w)
                 : "memory");
}

// ---------------- final scale + bias -----------------------------------------
__global__ void k_final(const float* __restrict__ b2, float* __restrict__ out) {
    int i = blockIdx.x * blockDim.x + threadIdx.x;
    if (i < NN * NC) out[i] = fmaf(out[i], g_dinv[i >> 4], b2[i & (NC - 1)]);
}

// ---------------- launch -----------------------------------------------------
extern "C" void kernel_launch(void* const* d_in, const int* in_sizes, int n_in,
                              void* d_out, int out_size) {
    const float* x  = (const float*)d_in[0];
    const int*   ei = (const int*)d_in[1];
    const float* W1 = (const float*)d_in[2];
    const float* b1 = (const float*)d_in[3];
    const float* W2 = (const float*)d_in[4];
    const float* b2 = (const float*)d_in[5];
    float* out = (float*)d_out;

    const int* src = ei;        // edge_index[0]
    const int* dst = ei + EE;   // edge_index[1]

    k_deg_init<<<(NN + 255) / 256, 256>>>();
    k_deg_count<<<(EE + 255) / 256, 256>>>(dst);
    k_dinv<<<(NN + 255) / 256, 256>>>();

    k_gemm1<<<(NN + 127) / 128, 256>>>(x, W1);      // h' + agg1 init

    k_agg1<<<EE / 8, 256>>>(src, dst);              // warp per edge

    k_gemm2<<<(NN + 15) / 16, 256>>>(b1, W2, out);  // z' + out init

    k_agg2<<<(EE * 4 + 255) / 256, 256>>>(src, dst, out);

    k_final<<<(NN * NC + 255) / 256, 256>>>(b2, out);
}